// round 2
// baseline (speedup 1.0000x reference)
#include <cuda_runtime.h>
#include <math.h>

// ---------------------------------------------------------------------------
// DAFCN forward, B=1024, T=50, F=48, D=512.
// Key insight: the attention branch (wq*/wk* convs, dvb, attended) is DEAD:
// combined[:, :, :10] selects only gcn_out. We compute only:
//   FFC branch (direct 31-bin DFT, 10-point inverse)  -> g_ffc scratch
//   GCN chain fused in one CTA per batch (SMEM-resident activations)
//   recon (idct = dct^T), fused, 2-layer MLP (only t<10 of output needed)
// ---------------------------------------------------------------------------

typedef unsigned long long ull;

#define PI_F 3.14159265358979f
#define W0_DCT 0.18257418583505537f  /* sqrt(1/30) */
#define W1_DCT 0.2581988897471611f   /* sqrt(2/30) */

__device__ float g_ffc[1024 * 48 * 10];  // [b][f48][t<10]

// ---- packed f32x2 helpers -------------------------------------------------
__device__ __forceinline__ ull pk2(float lo, float hi) {
    ull r;
    asm("mov.b64 %0, {%1, %2};" : "=l"(r) : "f"(lo), "f"(hi));
    return r;
}
__device__ __forceinline__ void fma2f(ull &d, ull a, ull b) {
    asm("fma.rn.f32x2 %0, %1, %2, %0;" : "+l"(d) : "l"(a), "l"(b));
}
__device__ __forceinline__ float2 up2(ull v) {
    float lo, hi;
    asm("mov.b64 {%0, %1}, %2;" : "=f"(lo), "=f"(hi) : "l"(v));
    return make_float2(lo, hi);
}

// ===========================================================================
// FFC kernel: one block per (b, g) with g = f48 % 16, c = f48 / 16.
// x[c,t], t<60 (t>=50 repeats t=49). rfft 31 bins -> 6x6 mix + relu ->
// 10-sample inverse + 3x3 local mix. Only t<10 of the output matters.
// ===========================================================================
__global__ void ffc_kernel(const float* __restrict__ seq,
                           const float* __restrict__ wl,
                           const float* __restrict__ wg) {
    int bx = blockIdx.x;
    int b = bx >> 4;
    int g = bx & 15;
    int tid = threadIdx.x;

    __shared__ float sXf[3][60];
    __shared__ float sV[6][31];
    __shared__ float sc[60], ss[60];
    __shared__ float sWg[36], sWl[9];

    if (tid < 60) {
        float a = 6.283185307179586f * (float)tid / 60.0f;
        sc[tid] = cosf(a);
        ss[tid] = sinf(a);
    }
    if (tid < 36) sWg[tid] = wg[tid];
    if (tid < 9)  sWl[tid] = wl[tid];
    for (int i = tid; i < 180; i += 64) {
        int c = i / 60, t = i % 60;
        int tsrc = (t < 50) ? t : 49;
        sXf[c][t] = seq[b * 2400 + tsrc * 48 + c * 16 + g];
    }
    __syncthreads();

    if (tid < 31) {
        int k = tid;
        float re0 = 0.f, re1 = 0.f, re2 = 0.f, im0 = 0.f, im1 = 0.f, im2 = 0.f;
        int idx = 0;
        for (int t = 0; t < 60; t++) {
            float co = sc[idx], si = ss[idx];
            float x0 = sXf[0][t], x1 = sXf[1][t], x2 = sXf[2][t];
            re0 += x0 * co; im0 -= x0 * si;
            re1 += x1 * co; im1 -= x1 * si;
            re2 += x2 * co; im2 -= x2 * si;
            idx += k; if (idx >= 60) idx -= 60;
        }
        float U[6] = {re0, re1, re2, im0, im1, im2};
        #pragma unroll
        for (int o = 0; o < 6; o++) {
            float a = 0.f;
            #pragma unroll
            for (int c = 0; c < 6; c++) a += sWg[o * 6 + c] * U[c];
            sV[o][k] = (a > 0.f) ? a : 0.f;
        }
    }
    __syncthreads();

    if (tid < 30) {
        int o = tid / 10, t = tid % 10;
        // irfft(n=60) at sample t: (1/60)(Re0 + (-1)^t Re30 + 2 sum(Re cos - Im sin))
        float spec = sV[o][0] + ((t & 1) ? -sV[o][30] : sV[o][30]);
        int idx = t;
        for (int k = 1; k < 30; k++) {
            spec += 2.0f * (sV[o][k] * sc[idx] - sV[o + 3][k] * ss[idx]);
            idx += t; if (idx >= 60) idx -= 60;
        }
        spec *= (1.0f / 60.0f);
        float v = spec;
        #pragma unroll
        for (int c = 0; c < 3; c++) v += sWl[o * 3 + c] * sXf[c][t];
        g_ffc[b * 480 + (o * 16 + g) * 10 + t] = v;
    }
}

// ===========================================================================
// GCN mega-kernel: 1 CTA per batch, 512 threads.
// SMEM: sX (48x512 activation y), sT (48x512 temp), sAtt (48x48), misc.
// Big GEMM (K=512, W in L2) and att-GEMM (K=48, T in SMEM) use f32x2 FMA,
// thread tile 3 rows x 16 cols (8 column-pair accumulators per row).
// ===========================================================================

__device__ __forceinline__ void gemm_main(const float* Xs,
                                          const float* __restrict__ Wg,
                                          float* dstT) {
    const int cg = threadIdx.x & 31;
    const int rg = threadIdx.x >> 5;
    const int r0 = rg * 3, n0 = cg * 16;
    ull acc[24];
    #pragma unroll
    for (int i = 0; i < 24; i++) acc[i] = 0ull;

    const float4* W4 = reinterpret_cast<const float4*>(Wg + n0);
    const float* x0p = Xs + r0 * 512;

    #pragma unroll 4
    for (int k = 0; k < 512; k++) {
        float4 wa = __ldg(W4 + k * 128);
        float4 wb = __ldg(W4 + k * 128 + 1);
        float4 wc = __ldg(W4 + k * 128 + 2);
        float4 wd = __ldg(W4 + k * 128 + 3);
        ull w[8];
        w[0] = pk2(wa.x, wa.y); w[1] = pk2(wa.z, wa.w);
        w[2] = pk2(wb.x, wb.y); w[3] = pk2(wb.z, wb.w);
        w[4] = pk2(wc.x, wc.y); w[5] = pk2(wc.z, wc.w);
        w[6] = pk2(wd.x, wd.y); w[7] = pk2(wd.z, wd.w);
        #pragma unroll
        for (int i = 0; i < 3; i++) {
            float xv = x0p[i * 512 + k];
            ull xp = pk2(xv, xv);
            #pragma unroll
            for (int j = 0; j < 8; j++) fma2f(acc[i * 8 + j], xp, w[j]);
        }
    }
    __syncthreads();
    #pragma unroll
    for (int i = 0; i < 3; i++) {
        float2* row = reinterpret_cast<float2*>(dstT + (r0 + i) * 512 + n0);
        #pragma unroll
        for (int j = 0; j < 8; j++) row[j] = up2(acc[i * 8 + j]);
    }
    __syncthreads();
}

// mode 0: sX = tanh(att@T + b)      (gc1)
// mode 1: sT = tanh(att@T + b)      (h1, in place)
// mode 2: sX += tanh(att@T + b)     (h2, residual)
__device__ __forceinline__ void att_stage(const float* sA, float* sTT,
                                          const float* sB, float* sXX,
                                          int mode) {
    const int cg = threadIdx.x & 31;
    const int rg = threadIdx.x >> 5;
    const int r0 = rg * 3, n0 = cg * 16;
    ull acc[24];
    #pragma unroll
    for (int i = 0; i < 24; i++) acc[i] = 0ull;

    #pragma unroll 4
    for (int m = 0; m < 48; m++) {
        const float4* tp = reinterpret_cast<const float4*>(sTT + m * 512 + n0);
        float4 ta = tp[0], tb = tp[1], tc = tp[2], td = tp[3];
        ull w[8];
        w[0] = pk2(ta.x, ta.y); w[1] = pk2(ta.z, ta.w);
        w[2] = pk2(tb.x, tb.y); w[3] = pk2(tb.z, tb.w);
        w[4] = pk2(tc.x, tc.y); w[5] = pk2(tc.z, tc.w);
        w[6] = pk2(td.x, td.y); w[7] = pk2(td.z, td.w);
        #pragma unroll
        for (int i = 0; i < 3; i++) {
            float av = sA[(r0 + i) * 48 + m];
            ull ap = pk2(av, av);
            #pragma unroll
            for (int j = 0; j < 8; j++) fma2f(acc[i * 8 + j], ap, w[j]);
        }
    }
    __syncthreads();
    #pragma unroll
    for (int i = 0; i < 3; i++) {
        #pragma unroll
        for (int j = 0; j < 8; j++) {
            float2 v = up2(acc[i * 8 + j]);
            float b0 = sB[n0 + 2 * j], b1 = sB[n0 + 2 * j + 1];
            float lo = tanhf(v.x + b0);
            float hi = tanhf(v.y + b1);
            int off = (r0 + i) * 512 + n0 + 2 * j;
            if (mode == 0)      { sXX[off] = lo;  sXX[off + 1] = hi; }
            else if (mode == 1) { sTT[off] = lo;  sTT[off + 1] = hi; }
            else                { sXX[off] += lo; sXX[off + 1] += hi; }
        }
    }
    __syncthreads();
}

#define SMEM_FLOATS (24576 + 24576 + 2304 + 480 + 512 + 1920 + 480)

__global__ void __launch_bounds__(512, 1)
gcn_kernel(const float* __restrict__ seq,
           const float* __restrict__ gc1_w,  const float* __restrict__ gc1_att,
           const float* __restrict__ gc1_b,  const float* __restrict__ gcb_w,
           const float* __restrict__ gcb_att,const float* __restrict__ gcb_b,
           const float* __restrict__ gc7_w,  const float* __restrict__ gc7_att,
           const float* __restrict__ gc7_b,  const float* __restrict__ mlp_w1,
           const float* __restrict__ mlp_w2, float* __restrict__ out) {
    extern __shared__ float sm[];
    float* sX    = sm;                    // 48*512
    float* sT    = sX + 24576;            // 48*512
    float* sAtt  = sT + 24576;            // 48*48
    float* sDct  = sAtt + 2304;           // 48*10
    float* sBias = sDct + 480;            // 512
    float* sFused= sBias + 512;           // 48*40
    float* sG7   = sFused + 1920;         // 48*10

    const int tid = threadIdx.x;
    const int b = blockIdx.x;
    const float* sq = seq + b * 2400;

    // ---- dct_in[f][d] = sum_{k<10} dct(d,k) seq[40+k,f] + (sum_{k>=10} dct(d,k)) seq[49,f]
    if (tid < 480) {
        int f = tid % 48, d = tid / 48;
        float wd = (d == 0) ? W0_DCT : W1_DCT;
        float acc = 0.f, Sd = 0.f;
        for (int k = 0; k < 30; k++) {
            float cv = wd * cosf(PI_F * ((float)k + 0.5f) * (float)d / 30.0f);
            if (k < 10) acc += cv * sq[(40 + k) * 48 + f];
            else        Sd  += cv;
        }
        acc += Sd * sq[49 * 48 + f];
        sDct[f * 10 + d] = acc;
    }
    for (int i = tid; i < 2304; i += 512) sAtt[i] = gc1_att[i];
    sBias[tid] = gc1_b[tid];
    __syncthreads();

    // ---- gc1: T = dct_in @ gc1_w  (K=10)
    {
        float w10[10];
        #pragma unroll
        for (int d = 0; d < 10; d++) w10[d] = gc1_w[d * 512 + tid];
        for (int f = 0; f < 48; f++) {
            float a = 0.f;
            #pragma unroll
            for (int d = 0; d < 10; d++) a += w10[d] * sDct[f * 10 + d];
            sT[f * 512 + tid] = a;
        }
    }
    __syncthreads();
    att_stage(sAtt, sT, sBias, sX, 0);    // sX = y = tanh(att@T + b)

    // ---- 4 gconv layers (2 stages x 2), residual every second layer
    for (int l = 0; l < 4; l++) {
        for (int i = tid; i < 2304; i += 512) sAtt[i] = gcb_att[l * 2304 + i];
        sBias[tid] = gcb_b[l * 512 + tid];
        const float* W = gcb_w + l * 262144;
        const float* src = (l & 1) ? sT : sX;
        gemm_main(src, W, sT);                       // sT = src @ W
        att_stage(sAtt, sT, sBias, sX, (l & 1) ? 2 : 1);
    }

    // ---- gc7: (48x10) = sX @ gc7_w, then att7 + bias + dct_in residual
    if (tid < 480) {
        int m = tid / 10, o = tid % 10;
        float a = 0.f;
        for (int k = 0; k < 512; k++) a += sX[m * 512 + k] * gc7_w[k * 10 + o];
        sG7[tid] = a;
    }
    __syncthreads();
    if (tid < 480) {
        int n = tid / 10, o = tid % 10;
        float a = gc7_b[o] + sDct[n * 10 + o];
        for (int m = 0; m < 48; m++) a += gc7_att[n * 48 + m] * sG7[m * 10 + o];
        sDct[n * 10 + o] = a;   // gcn_out, own element only
    }
    __syncthreads();

    // ---- fused[f][t]: t<30 = idct(gcn_out) (idct = dct^T), t>=30 = ffc
    for (int i = tid; i < 1920; i += 512) {
        int f = i % 48, t = i / 48;
        float v;
        if (t < 30) {
            v = 0.f;
            #pragma unroll
            for (int d = 0; d < 10; d++) {
                float wd = (d == 0) ? W0_DCT : W1_DCT;
                v += wd * cosf(PI_F * ((float)t + 0.5f) * (float)d / 30.0f)
                        * sDct[f * 10 + d];
            }
        } else {
            v = g_ffc[b * 480 + f * 10 + (t - 30)];
        }
        sFused[f * 40 + t] = v;
    }
    __syncthreads();

    // ---- MLP layer 1: h[f][o<256] = relu(fused @ w1^T)  -> store in sT
    {
        int o = tid & 255;
        int fg = tid >> 8;   // 0 or 1
        float w1r[40];
        #pragma unroll
        for (int t = 0; t < 40; t++) w1r[t] = mlp_w1[o * 40 + t];
        for (int f = fg * 24; f < fg * 24 + 24; f++) {
            float a = 0.f;
            #pragma unroll
            for (int t = 0; t < 40; t++) a += w1r[t] * sFused[f * 40 + t];
            sT[f * 256 + o] = (a > 0.f) ? a : 0.f;
        }
    }
    __syncthreads();

    // ---- MLP layer 2, only t'<10 needed; out[b][t'][0][f]
    if (tid < 480) {
        int f = tid / 10, t2 = tid % 10;
        float a = 0.f;
        for (int o = 0; o < 256; o++) a += sT[f * 256 + o] * mlp_w2[t2 * 256 + o];
        out[b * 480 + t2 * 48 + f] = a;
    }
}

// ===========================================================================
extern "C" void kernel_launch(void* const* d_in, const int* in_sizes, int n_in,
                              void* d_out, int out_size) {
    const float* seq     = (const float*)d_in[0];
    // d_in[1..4] (wq1,wq2,wk1,wk2) are dead: attention branch unused by output
    const float* gc1_w   = (const float*)d_in[5];
    const float* gc1_att = (const float*)d_in[6];
    const float* gc1_b   = (const float*)d_in[7];
    const float* gcb_w   = (const float*)d_in[8];
    const float* gcb_att = (const float*)d_in[9];
    const float* gcb_b   = (const float*)d_in[10];
    const float* gc7_w   = (const float*)d_in[11];
    const float* gc7_att = (const float*)d_in[12];
    const float* gc7_b   = (const float*)d_in[13];
    const float* mlp_w1  = (const float*)d_in[14];
    const float* mlp_w2  = (const float*)d_in[15];
    const float* ffc_wl  = (const float*)d_in[16];
    const float* ffc_wg  = (const float*)d_in[17];
    float* out = (float*)d_out;

    int B = in_sizes[0] / 2400;
    size_t smem = SMEM_FLOATS * sizeof(float);
    cudaFuncSetAttribute(gcn_kernel, cudaFuncAttributeMaxDynamicSharedMemorySize,
                         (int)smem);

    ffc_kernel<<<B * 16, 64>>>(seq, ffc_wl, ffc_wg);
    gcn_kernel<<<B, 512, smem>>>(seq, gc1_w, gc1_att, gc1_b, gcb_w, gcb_att,
                                 gcb_b, gc7_w, gc7_att, gc7_b, mlp_w1, mlp_w2,
                                 out);
}

// round 4
// speedup vs baseline: 2.6868x; 2.6868x over previous
#include <cuda_runtime.h>
#include <math.h>

// ---------------------------------------------------------------------------
// DAFCN forward, B=1024, T=50, F=48, D=512.
// Attention branch (wq*/wk*, dvb, attended) is dead: combined[:, :, :10]
// selects only gcn_out. Compute FFC (direct DFT) + GCN chain + MLP.
// R2: gconv reassociated to (att@X)@W; 12x4 thread tiles; vectorized LDS;
//     194KB SMEM (L1D ~34KB); W read once per CTA per layer via L1 reuse.
// ---------------------------------------------------------------------------

typedef unsigned long long ull;

#define PI_F 3.14159265358979f
#define W0_DCT 0.18257418583505537f  /* sqrt(1/30) */
#define W1_DCT 0.2581988897471611f   /* sqrt(2/30) */

__device__ float g_ffc[1024 * 48 * 10];  // [b][f48][t<10]

// ---- packed f32x2 helpers -------------------------------------------------
__device__ __forceinline__ ull pk2(float lo, float hi) {
    ull r;
    asm("mov.b64 %0, {%1, %2};" : "=l"(r) : "f"(lo), "f"(hi));
    return r;
}
__device__ __forceinline__ void fma2f(ull &d, ull a, ull b) {
    asm("fma.rn.f32x2 %0, %1, %2, %0;" : "+l"(d) : "l"(a), "l"(b));
}
__device__ __forceinline__ float2 up2(ull v) {
    float lo, hi;
    asm("mov.b64 {%0, %1}, %2;" : "=f"(lo), "=f"(hi) : "l"(v));
    return make_float2(lo, hi);
}

// ===========================================================================
// FFC kernel: one block per (b, g), g = f48 % 16, c = f48 / 16.
// ===========================================================================
__global__ void ffc_kernel(const float* __restrict__ seq,
                           const float* __restrict__ wl,
                           const float* __restrict__ wg) {
    int bx = blockIdx.x;
    int b = bx >> 4;
    int g = bx & 15;
    int tid = threadIdx.x;

    __shared__ float sXf[3][60];
    __shared__ float sV[6][31];
    __shared__ float sc[60], ss[60];
    __shared__ float sWg[36], sWl[9];

    if (tid < 60) {
        float a = 6.283185307179586f * (float)tid / 60.0f;
        sc[tid] = cosf(a);
        ss[tid] = sinf(a);
    }
    if (tid < 36) sWg[tid] = wg[tid];
    if (tid < 9)  sWl[tid] = wl[tid];
    for (int i = tid; i < 180; i += 64) {
        int c = i / 60, t = i % 60;
        int tsrc = (t < 50) ? t : 49;
        sXf[c][t] = seq[b * 2400 + tsrc * 48 + c * 16 + g];
    }
    __syncthreads();

    if (tid < 31) {
        int k = tid;
        float re0 = 0.f, re1 = 0.f, re2 = 0.f, im0 = 0.f, im1 = 0.f, im2 = 0.f;
        int idx = 0;
        for (int t = 0; t < 60; t++) {
            float co = sc[idx], si = ss[idx];
            float x0 = sXf[0][t], x1 = sXf[1][t], x2 = sXf[2][t];
            re0 += x0 * co; im0 -= x0 * si;
            re1 += x1 * co; im1 -= x1 * si;
            re2 += x2 * co; im2 -= x2 * si;
            idx += k; if (idx >= 60) idx -= 60;
        }
        float U[6] = {re0, re1, re2, im0, im1, im2};
        #pragma unroll
        for (int o = 0; o < 6; o++) {
            float a = 0.f;
            #pragma unroll
            for (int c = 0; c < 6; c++) a += sWg[o * 6 + c] * U[c];
            sV[o][k] = (a > 0.f) ? a : 0.f;
        }
    }
    __syncthreads();

    if (tid < 30) {
        int o = tid / 10, t = tid % 10;
        float spec = sV[o][0] + ((t & 1) ? -sV[o][30] : sV[o][30]);
        int idx = t;
        for (int k = 1; k < 30; k++) {
            spec += 2.0f * (sV[o][k] * sc[idx] - sV[o + 3][k] * ss[idx]);
            idx += t; if (idx >= 60) idx -= 60;
        }
        spec *= (1.0f / 60.0f);
        float v = spec;
        #pragma unroll
        for (int c = 0; c < 3; c++) v += sWl[o * 3 + c] * sXf[c][t];
        g_ffc[b * 480 + (o * 16 + g) * 10 + t] = v;
    }
}

// ===========================================================================
// GCN mega-kernel: 1 CTA per batch, 512 threads.
// Thread tile: 12 rows x 4 cols. cgid = tid & 127 (col group), rg = tid >> 7.
// ===========================================================================

// dst = tanh(Z @ W + bias)   (mode 0: store;  mode 1: dst += ...)
// Accumulate fully in registers, barrier, then write -> in-place safe.
__device__ __forceinline__ void big_gemm(const float* Z,
                                         const float* __restrict__ W,
                                         const float* __restrict__ bias,
                                         float* dst, int mode) {
    const int cgid = threadIdx.x & 127;
    const int rg = threadIdx.x >> 7;
    const int r0 = rg * 12, n0 = cgid * 4;
    ull acc[24];
    #pragma unroll
    for (int i = 0; i < 24; i++) acc[i] = 0ull;

    const float4* Wb = reinterpret_cast<const float4*>(W + n0);

    for (int k4 = 0; k4 < 128; k4++) {
        if ((k4 & 3) == 0) __syncthreads();   // keep warps in L1-reuse lockstep
        float4 w0 = __ldg(Wb + (k4 * 4 + 0) * 128);
        float4 w1 = __ldg(Wb + (k4 * 4 + 1) * 128);
        float4 w2 = __ldg(Wb + (k4 * 4 + 2) * 128);
        float4 w3 = __ldg(Wb + (k4 * 4 + 3) * 128);
        ull wp[8];
        wp[0] = pk2(w0.x, w0.y); wp[1] = pk2(w0.z, w0.w);
        wp[2] = pk2(w1.x, w1.y); wp[3] = pk2(w1.z, w1.w);
        wp[4] = pk2(w2.x, w2.y); wp[5] = pk2(w2.z, w2.w);
        wp[6] = pk2(w3.x, w3.y); wp[7] = pk2(w3.z, w3.w);
        #pragma unroll
        for (int i = 0; i < 12; i++) {
            float4 xv = *reinterpret_cast<const float4*>(Z + (r0 + i) * 512 + k4 * 4);
            ull a;
            a = pk2(xv.x, xv.x); fma2f(acc[2*i], a, wp[0]); fma2f(acc[2*i+1], a, wp[1]);
            a = pk2(xv.y, xv.y); fma2f(acc[2*i], a, wp[2]); fma2f(acc[2*i+1], a, wp[3]);
            a = pk2(xv.z, xv.z); fma2f(acc[2*i], a, wp[4]); fma2f(acc[2*i+1], a, wp[5]);
            a = pk2(xv.w, xv.w); fma2f(acc[2*i], a, wp[6]); fma2f(acc[2*i+1], a, wp[7]);
        }
    }
    __syncthreads();   // all reads of Z done -> safe to overwrite
    float4 bv = __ldg(reinterpret_cast<const float4*>(bias + n0));
    #pragma unroll
    for (int i = 0; i < 12; i++) {
        float2 v0 = up2(acc[2*i]), v1 = up2(acc[2*i+1]);
        float o0 = tanhf(v0.x + bv.x);
        float o1 = tanhf(v0.y + bv.y);
        float o2 = tanhf(v1.x + bv.z);
        float o3 = tanhf(v1.y + bv.w);
        float4* p = reinterpret_cast<float4*>(dst + (r0 + i) * 512 + n0);
        if (mode == 0) {
            *p = make_float4(o0, o1, o2, o3);
        } else {
            float4 old = *p;
            *p = make_float4(old.x + o0, old.y + o1, old.z + o2, old.w + o3);
        }
    }
    __syncthreads();
}

// dst = att @ Y   (att 48x48 from gmem, Y 48x512 in SMEM). In-place safe.
__device__ __forceinline__ void att_mul(const float* Y,
                                        const float* __restrict__ att,
                                        float* dst) {
    const int cgid = threadIdx.x & 127;
    const int rg = threadIdx.x >> 7;
    const int r0 = rg * 12, n0 = cgid * 4;
    ull acc[24];
    #pragma unroll
    for (int i = 0; i < 24; i++) acc[i] = 0ull;

    for (int m4 = 0; m4 < 12; m4++) {
        float4 t0 = *reinterpret_cast<const float4*>(Y + (m4 * 4 + 0) * 512 + n0);
        float4 t1 = *reinterpret_cast<const float4*>(Y + (m4 * 4 + 1) * 512 + n0);
        float4 t2 = *reinterpret_cast<const float4*>(Y + (m4 * 4 + 2) * 512 + n0);
        float4 t3 = *reinterpret_cast<const float4*>(Y + (m4 * 4 + 3) * 512 + n0);
        ull tp[8];
        tp[0] = pk2(t0.x, t0.y); tp[1] = pk2(t0.z, t0.w);
        tp[2] = pk2(t1.x, t1.y); tp[3] = pk2(t1.z, t1.w);
        tp[4] = pk2(t2.x, t2.y); tp[5] = pk2(t2.z, t2.w);
        tp[6] = pk2(t3.x, t3.y); tp[7] = pk2(t3.z, t3.w);
        #pragma unroll
        for (int i = 0; i < 12; i++) {
            float4 av = __ldg(reinterpret_cast<const float4*>(att + (r0 + i) * 48 + m4 * 4));
            ull a;
            a = pk2(av.x, av.x); fma2f(acc[2*i], a, tp[0]); fma2f(acc[2*i+1], a, tp[1]);
            a = pk2(av.y, av.y); fma2f(acc[2*i], a, tp[2]); fma2f(acc[2*i+1], a, tp[3]);
            a = pk2(av.z, av.z); fma2f(acc[2*i], a, tp[4]); fma2f(acc[2*i+1], a, tp[5]);
            a = pk2(av.w, av.w); fma2f(acc[2*i], a, tp[6]); fma2f(acc[2*i+1], a, tp[7]);
        }
    }
    __syncthreads();   // all reads of Y done -> in-place safe
    #pragma unroll
    for (int i = 0; i < 12; i++) {
        float2 v0 = up2(acc[2*i]), v1 = up2(acc[2*i+1]);
        *reinterpret_cast<float4*>(dst + (r0 + i) * 512 + n0) =
            make_float4(v0.x, v0.y, v1.x, v1.y);
    }
    __syncthreads();
}

#define SMEM_FLOATS (24576 + 24576 + 480)

__global__ void __launch_bounds__(512, 1)
gcn_kernel(const float* __restrict__ seq,
           const float* __restrict__ gc1_w,  const float* __restrict__ gc1_att,
           const float* __restrict__ gc1_b,  const float* __restrict__ gcb_w,
           const float* __restrict__ gcb_att,const float* __restrict__ gcb_b,
           const float* __restrict__ gc7_w,  const float* __restrict__ gc7_att,
           const float* __restrict__ gc7_b,  const float* __restrict__ mlp_w1,
           const float* __restrict__ mlp_w2, float* __restrict__ out) {
    extern __shared__ float sm[];
    float* sX   = sm;            // 48*512 (y)
    float* sZ   = sX + 24576;    // 48*512 (att@x / h)
    float* sDct = sZ + 24576;    // 48*10

    const int tid = threadIdx.x;
    const int b = blockIdx.x;
    const float* sq = seq + b * 2400;

    // ---- dct_in[f][d]
    if (tid < 480) {
        int f = tid % 48, d = tid / 48;
        float wd = (d == 0) ? W0_DCT : W1_DCT;
        float acc = 0.f, Sd = 0.f;
        for (int k = 0; k < 30; k++) {
            float cv = wd * cosf(PI_F * ((float)k + 0.5f) * (float)d / 30.0f);
            if (k < 10) acc += cv * sq[(40 + k) * 48 + f];
            else        Sd  += cv;
        }
        acc += Sd * sq[49 * 48 + f];
        sDct[f * 10 + d] = acc;
    }
    __syncthreads();

    // ---- gc1 reassociated: Z1 = att1 @ dct_in  (48x10, temp in sZ)
    if (tid < 480) {
        int n = tid / 10, d = tid % 10;
        float a = 0.f;
        for (int m = 0; m < 48; m++) a += __ldg(gc1_att + n * 48 + m) * sDct[m * 10 + d];
        sZ[n * 10 + d] = a;
    }
    __syncthreads();
    // y = tanh(Z1 @ gc1_w + b1)
    {
        float w10[10];
        #pragma unroll
        for (int d = 0; d < 10; d++) w10[d] = __ldg(gc1_w + d * 512 + tid);
        float bb = __ldg(gc1_b + tid);
        for (int n = 0; n < 48; n++) {
            float a = bb;
            #pragma unroll
            for (int d = 0; d < 10; d++) a += w10[d] * sZ[n * 10 + d];
            sX[n * 512 + tid] = tanhf(a);
        }
    }
    __syncthreads();

    // ---- 4 gconv layers: h = tanh((att@src)@W + b); odd layers: y += h
    #pragma unroll 1
    for (int l = 0; l < 4; l++) {
        const float* att  = gcb_att + l * 2304;
        const float* W    = gcb_w   + l * 262144;
        const float* bias = gcb_b   + l * 512;
        const float* src  = (l & 1) ? sZ : sX;
        att_mul(src, att, sZ);
        big_gemm(sZ, W, bias, (l & 1) ? sX : sZ, l & 1);
    }

    // ---- gc7: Z7 = att7 @ y; gcn_out = Z7 @ gc7_w + b7 + dct_in
    att_mul(sX, gc7_att, sZ);
    if (tid < 480) {
        int n = tid / 10, o = tid % 10;
        float a0 = __ldg(gc7_b + o) + sDct[tid], a1 = 0.f, a2 = 0.f, a3 = 0.f;
        const float* zr = sZ + n * 512;
        for (int k = 0; k < 512; k += 4) {
            a0 += zr[k    ] * __ldg(gc7_w + (k    ) * 10 + o);
            a1 += zr[k + 1] * __ldg(gc7_w + (k + 1) * 10 + o);
            a2 += zr[k + 2] * __ldg(gc7_w + (k + 2) * 10 + o);
            a3 += zr[k + 3] * __ldg(gc7_w + (k + 3) * 10 + o);
        }
        sDct[tid] = a0 + a1 + a2 + a3;   // own element only
    }
    __syncthreads();

    // ---- fused[f][t] (overlay in sZ): t<30 idct, t>=30 ffc
    float* sFused = sZ;          // 1920 floats
    float* sH     = sZ + 2048;   // 48*256 floats
    for (int i = tid; i < 1920; i += 512) {
        int f = i % 48, t = i / 48;
        float v;
        if (t < 30) {
            v = 0.f;
            #pragma unroll
            for (int d = 0; d < 10; d++) {
                float wd = (d == 0) ? W0_DCT : W1_DCT;
                v += wd * cosf(PI_F * ((float)t + 0.5f) * (float)d / 30.0f)
                        * sDct[f * 10 + d];
            }
        } else {
            v = g_ffc[b * 480 + f * 10 + (t - 30)];
        }
        sFused[f * 40 + t] = v;
    }
    __syncthreads();

    // ---- MLP layer 1
    {
        int o = tid & 255;
        int fg = tid >> 8;
        float w1r[40];
        #pragma unroll
        for (int t = 0; t < 40; t++) w1r[t] = __ldg(mlp_w1 + o * 40 + t);
        for (int f = fg * 24; f < fg * 24 + 24; f++) {
            float a = 0.f;
            #pragma unroll
            for (int t = 0; t < 40; t++) a += w1r[t] * sFused[f * 40 + t];
            sH[f * 256 + o] = (a > 0.f) ? a : 0.f;
        }
    }
    __syncthreads();

    // ---- MLP layer 2 (only t'<10); out[b][t'][0][f]
    if (tid < 480) {
        int f = tid / 10, t2 = tid % 10;
        float a0 = 0.f, a1 = 0.f, a2 = 0.f, a3 = 0.f;
        const float* hr = sH + f * 256;
        const float* w2 = mlp_w2 + t2 * 256;
        for (int o = 0; o < 256; o += 4) {
            a0 += hr[o    ] * __ldg(w2 + o);
            a1 += hr[o + 1] * __ldg(w2 + o + 1);
            a2 += hr[o + 2] * __ldg(w2 + o + 2);
            a3 += hr[o + 3] * __ldg(w2 + o + 3);
        }
        out[b * 480 + t2 * 48 + f] = a0 + a1 + a2 + a3;
    }
}

// ===========================================================================
extern "C" void kernel_launch(void* const* d_in, const int* in_sizes, int n_in,
                              void* d_out, int out_size) {
    const float* seq     = (const float*)d_in[0];
    const float* gc1_w   = (const float*)d_in[5];
    const float* gc1_att = (const float*)d_in[6];
    const float* gc1_b   = (const float*)d_in[7];
    const float* gcb_w   = (const float*)d_in[8];
    const float* gcb_att = (const float*)d_in[9];
    const float* gcb_b   = (const float*)d_in[10];
    const float* gc7_w   = (const float*)d_in[11];
    const float* gc7_att = (const float*)d_in[12];
    const float* gc7_b   = (const float*)d_in[13];
    const float* mlp_w1  = (const float*)d_in[14];
    const float* mlp_w2  = (const float*)d_in[15];
    const float* ffc_wl  = (const float*)d_in[16];
    const float* ffc_wg  = (const float*)d_in[17];
    float* out = (float*)d_out;

    int B = in_sizes[0] / 2400;
    size_t smem = SMEM_FLOATS * sizeof(float);
    cudaFuncSetAttribute(gcn_kernel, cudaFuncAttributeMaxDynamicSharedMemorySize,
                         (int)smem);

    ffc_kernel<<<B * 16, 64>>>(seq, ffc_wl, ffc_wg);
    gcn_kernel<<<B, 512, smem>>>(seq, gc1_w, gc1_att, gc1_b, gcb_w, gcb_att,
                                 gcb_b, gc7_w, gc7_att, gc7_b, mlp_w1, mlp_w2,
                                 out);
}